// round 1
// baseline (speedup 1.0000x reference)
#include <cuda_runtime.h>
#include <math.h>

#define TPB 256

// scratch: x1 = shortcut + attn branch  (16*128*128*96 floats = ~100MB)
static __device__ float g_x1[16 * 128 * 128 * 96];

// ---------------- kernel 1: LN1 + shifted-window attention + proj + residual ----------------
constexpr int HS1    = 98;                 // padded row stride for 96-col tiles
constexpr int OFF_H  = 0;                  // LN'd window tokens      64 x HS1
constexpr int OFF_W  = OFF_H  + 64 * HS1;  // staged weights          96 x 96
constexpr int OFF_Q  = OFF_W  + 96 * 96;   // per-head Q              64 x 33
constexpr int OFF_K  = OFF_Q  + 64 * 33;   // per-head K              64 x 33
constexpr int OFF_V  = OFF_K  + 64 * 33;   // per-head V              64 x 33
constexpr int OFF_S  = OFF_V  + 64 * 33;   // scores / probs          64 x 65
constexpr int OFF_O  = OFF_S  + 64 * 65;   // concat head outputs     64 x HS1
constexpr int OFF_RPB= OFF_O  + 64 * HS1;  // rel-pos table           225 x 3
constexpr int OFF_REG= OFF_RPB + 675;      // region id per token     64 (int)
constexpr int OFF_SRC= OFF_REG + 64;       // gathered row index      64 (int)
constexpr int OFF_INV= OFF_SRC + 64;       // 1/rowsum                64
constexpr int SM1_FLOATS = OFF_INV + 64;

__global__ __launch_bounds__(TPB) void attn_kernel(
    const float* __restrict__ x,
    const float* __restrict__ n1w, const float* __restrict__ n1b,
    const float* __restrict__ qkvw, const float* __restrict__ qkvb,
    const float* __restrict__ rpb,
    const float* __restrict__ pw,  const float* __restrict__ pb)
{
    extern __shared__ float sm[];
    float* shH  = sm + OFF_H;
    float* sW   = sm + OFF_W;
    float* sQ   = sm + OFF_Q;
    float* sK   = sm + OFF_K;
    float* sV   = sm + OFF_V;
    float* sS   = sm + OFF_S;
    float* sO   = sm + OFF_O;
    float* sRPB = sm + OFF_RPB;
    int*   sReg = (int*)(sm + OFF_REG);
    int*   sSrc = (int*)(sm + OFF_SRC);
    float* sInv = sm + OFF_INV;

    const int tid = threadIdx.x;
    const int bw  = blockIdx.x;
    const int bb  = bw >> 8;          // batch
    const int wh  = (bw >> 4) & 15;   // window row
    const int ww  = bw & 15;          // window col
    const int baseRow = bb * (128 * 128);

    // per-token metadata: gathered row index (with shift roll) + shift-mask region id
    if (tid < 64) {
        int i = tid >> 3, j = tid & 7;
        int hr = wh * 8 + i, wr = ww * 8 + j;       // rolled-grid coords
        int hs = (hr + 4) & 127, ws = (wr + 4) & 127;  // source coords in x
        sSrc[tid] = baseRow + hs * 128 + ws;
        int rh = hr < 120 ? 0 : (hr < 124 ? 1 : 2);
        int rw = wr < 120 ? 0 : (wr < 124 ? 1 : 2);
        sReg[tid] = rh * 3 + rw;
    }
    for (int t = tid; t < 675; t += TPB) sRPB[t] = rpb[t];

    // gather + LayerNorm1: warp handles 8 rows, 3 elems/lane
    {
        const int warp = tid >> 5, lane = tid & 31;
        float w0 = n1w[lane], w1 = n1w[lane + 32], w2 = n1w[lane + 64];
        float c0 = n1b[lane], c1 = n1b[lane + 32], c2 = n1b[lane + 64];
        for (int rr = 0; rr < 8; ++rr) {
            int n = warp * 8 + rr;
            int i = n >> 3, j = n & 7;
            int hs = (wh * 8 + i + 4) & 127, ws = (ww * 8 + j + 4) & 127;
            const float* px = x + (size_t)(baseRow + hs * 128 + ws) * 96;
            float v0 = px[lane], v1 = px[lane + 32], v2 = px[lane + 64];
            float s = v0 + v1 + v2, s2 = v0 * v0 + v1 * v1 + v2 * v2;
            #pragma unroll
            for (int o = 16; o; o >>= 1) {
                s  += __shfl_xor_sync(0xffffffffu, s, o);
                s2 += __shfl_xor_sync(0xffffffffu, s2, o);
            }
            float mu = s * (1.f / 96.f);
            float rs = rsqrtf(s2 * (1.f / 96.f) - mu * mu + 1e-5f);
            shH[n * HS1 + lane]      = (v0 - mu) * rs * w0 + c0;
            shH[n * HS1 + lane + 32] = (v1 - mu) * rs * w1 + c1;
            shH[n * HS1 + lane + 64] = (v2 - mu) * rs * w2 + c2;
        }
    }
    __syncthreads();

    const int rt = tid >> 4, ct = tid & 15;   // 16x16 thread grid
    const int r0 = rt * 4, c0 = ct * 6;       // 4 rows x 6 cols per thread
    const float scale = 0.17677669529663687f; // 1/sqrt(32)

    for (int h = 0; h < 3; ++h) {
        // stage per-head qkv weights: cols 0-31 = Q, 32-63 = K, 64-95 = V
        for (int t = tid; t < 96 * 96; t += TPB) {
            int k = t / 96, c = t - k * 96;
            int sec = c >> 5, d = c & 31;
            sW[t] = qkvw[k * 288 + sec * 96 + h * 32 + d];
        }
        __syncthreads();

        // QKV GEMM: (64x96) = shH(64x96) @ sW(96x96)
        {
            float acc[4][6] = {};
            #pragma unroll 4
            for (int k = 0; k < 96; ++k) {
                float a0 = shH[(r0 + 0) * HS1 + k];
                float a1 = shH[(r0 + 1) * HS1 + k];
                float a2 = shH[(r0 + 2) * HS1 + k];
                float a3 = shH[(r0 + 3) * HS1 + k];
                const float2* pb2 = (const float2*)(sW + k * 96 + c0);
                float2 q0 = pb2[0], q1 = pb2[1], q2 = pb2[2];
                float bv[6] = {q0.x, q0.y, q1.x, q1.y, q2.x, q2.y};
                #pragma unroll
                for (int j = 0; j < 6; ++j) {
                    acc[0][j] += a0 * bv[j];
                    acc[1][j] += a1 * bv[j];
                    acc[2][j] += a2 * bv[j];
                    acc[3][j] += a3 * bv[j];
                }
            }
            #pragma unroll
            for (int j = 0; j < 6; ++j) {
                int c = c0 + j, sec = c >> 5, d = c & 31;
                float bias = qkvb[sec * 96 + h * 32 + d];
                float mul  = (sec == 0) ? scale : 1.f;
                float* dst = (sec == 0) ? sQ : (sec == 1) ? sK : sV;
                #pragma unroll
                for (int i = 0; i < 4; ++i)
                    dst[(r0 + i) * 33 + d] = (acc[i][j] + bias) * mul;
            }
        }
        __syncthreads();

        // S = Q K^T (+ rel-pos bias + shift mask), 4x4 per thread
        {
            int c0s = ct * 4;
            float acc[4][4] = {};
            #pragma unroll 4
            for (int d = 0; d < 32; ++d) {
                float a0 = sQ[(r0 + 0) * 33 + d];
                float a1 = sQ[(r0 + 1) * 33 + d];
                float a2 = sQ[(r0 + 2) * 33 + d];
                float a3 = sQ[(r0 + 3) * 33 + d];
                float b0 = sK[(c0s + 0) * 33 + d];
                float b1 = sK[(c0s + 1) * 33 + d];
                float b2 = sK[(c0s + 2) * 33 + d];
                float b3 = sK[(c0s + 3) * 33 + d];
                acc[0][0] += a0 * b0; acc[0][1] += a0 * b1; acc[0][2] += a0 * b2; acc[0][3] += a0 * b3;
                acc[1][0] += a1 * b0; acc[1][1] += a1 * b1; acc[1][2] += a1 * b2; acc[1][3] += a1 * b3;
                acc[2][0] += a2 * b0; acc[2][1] += a2 * b1; acc[2][2] += a2 * b2; acc[2][3] += a2 * b3;
                acc[3][0] += a3 * b0; acc[3][1] += a3 * b1; acc[3][2] += a3 * b2; acc[3][3] += a3 * b3;
            }
            #pragma unroll
            for (int i = 0; i < 4; ++i) {
                int n = r0 + i, iq = n >> 3, jq = n & 7, regn = sReg[n];
                #pragma unroll
                for (int j = 0; j < 4; ++j) {
                    int m = c0s + j, im = m >> 3, jm = m & 7;
                    float bias = sRPB[((iq - im + 7) * 15 + (jq - jm + 7)) * 3 + h];
                    float mv = (regn == sReg[m]) ? 0.f : -100.f;
                    sS[n * 65 + m] = acc[i][j] + bias + mv;
                }
            }
        }
        __syncthreads();

        // softmax: 4 threads per row, 16 elems each; defer 1/sum to PV epilogue
        {
            int row = tid >> 2, sub = tid & 3;
            float* prow = sS + row * 65 + sub * 16;
            float mx = prow[0];
            #pragma unroll
            for (int t = 1; t < 16; ++t) mx = fmaxf(mx, prow[t]);
            mx = fmaxf(mx, __shfl_xor_sync(0xffffffffu, mx, 1));
            mx = fmaxf(mx, __shfl_xor_sync(0xffffffffu, mx, 2));
            float sum = 0.f;
            #pragma unroll
            for (int t = 0; t < 16; ++t) {
                float e = __expf(prow[t] - mx);
                prow[t] = e;
                sum += e;
            }
            sum += __shfl_xor_sync(0xffffffffu, sum, 1);
            sum += __shfl_xor_sync(0xffffffffu, sum, 2);
            if (sub == 0) sInv[row] = 1.f / sum;
        }
        __syncthreads();

        // O = P V, 2x4 per thread, write into concat buffer at head offset
        {
            int rt2 = tid >> 3, ct2 = tid & 7;
            int ro = rt2 * 2, co = ct2 * 4;
            float acc[2][4] = {};
            #pragma unroll 4
            for (int m = 0; m < 64; ++m) {
                float a0 = sS[ro * 65 + m], a1 = sS[(ro + 1) * 65 + m];
                float b0 = sV[m * 33 + co + 0];
                float b1 = sV[m * 33 + co + 1];
                float b2 = sV[m * 33 + co + 2];
                float b3 = sV[m * 33 + co + 3];
                acc[0][0] += a0 * b0; acc[0][1] += a0 * b1; acc[0][2] += a0 * b2; acc[0][3] += a0 * b3;
                acc[1][0] += a1 * b0; acc[1][1] += a1 * b1; acc[1][2] += a1 * b2; acc[1][3] += a1 * b3;
            }
            float s0 = sInv[ro], s1 = sInv[ro + 1];
            #pragma unroll
            for (int j = 0; j < 4; ++j) {
                sO[ro * HS1 + h * 32 + co + j]       = acc[0][j] * s0;
                sO[(ro + 1) * HS1 + h * 32 + co + j] = acc[1][j] * s1;
            }
        }
        __syncthreads();
    }

    // proj + residual, scatter back (scatter row == gather row)
    for (int t = tid; t < 96 * 96; t += TPB) sW[t] = pw[t];
    __syncthreads();
    {
        float acc[4][6] = {};
        #pragma unroll 4
        for (int k = 0; k < 96; ++k) {
            float a0 = sO[(r0 + 0) * HS1 + k];
            float a1 = sO[(r0 + 1) * HS1 + k];
            float a2 = sO[(r0 + 2) * HS1 + k];
            float a3 = sO[(r0 + 3) * HS1 + k];
            const float2* pb2 = (const float2*)(sW + k * 96 + c0);
            float2 q0 = pb2[0], q1 = pb2[1], q2 = pb2[2];
            float bv[6] = {q0.x, q0.y, q1.x, q1.y, q2.x, q2.y};
            #pragma unroll
            for (int j = 0; j < 6; ++j) {
                acc[0][j] += a0 * bv[j];
                acc[1][j] += a1 * bv[j];
                acc[2][j] += a2 * bv[j];
                acc[3][j] += a3 * bv[j];
            }
        }
        #pragma unroll
        for (int i = 0; i < 4; ++i) {
            int row = sSrc[r0 + i];
            const float* px = x + (size_t)row * 96;
            float* pd = g_x1 + (size_t)row * 96;
            #pragma unroll
            for (int j = 0; j < 6; ++j) {
                int c = c0 + j;
                pd[c] = acc[i][j] + pb[c] + px[c];
            }
        }
    }
}

// ---------------- kernel 2: LN2 + MLP (fc1 -> exact GELU -> fc2) + residual ----------------
constexpr int HS2   = 98;
constexpr int HIDS  = 386;                     // padded 384
constexpr int K2_OFF_H   = 0;
constexpr int K2_OFF_W   = 64 * HS2;           // 96x96 staged weight chunk
constexpr int K2_OFF_HID = K2_OFF_W + 96 * 96; // 64 x HIDS hidden
constexpr int SM2_FLOATS = K2_OFF_HID + 64 * HIDS;

__global__ __launch_bounds__(TPB) void mlp_kernel(
    const float* __restrict__ n2w, const float* __restrict__ n2b,
    const float* __restrict__ w1,  const float* __restrict__ b1,
    const float* __restrict__ w2,  const float* __restrict__ b2,
    float* __restrict__ out)
{
    extern __shared__ float sm[];
    float* shH  = sm + K2_OFF_H;
    float* sW   = sm + K2_OFF_W;
    float* sHid = sm + K2_OFF_HID;

    const int tid = threadIdx.x;
    const int gr0 = blockIdx.x * 64;

    // LN2
    {
        const int warp = tid >> 5, lane = tid & 31;
        float w0 = n2w[lane], wA = n2w[lane + 32], wB = n2w[lane + 64];
        float c0 = n2b[lane], cA = n2b[lane + 32], cB = n2b[lane + 64];
        for (int rr = 0; rr < 8; ++rr) {
            int n = warp * 8 + rr;
            const float* px = g_x1 + (size_t)(gr0 + n) * 96;
            float v0 = px[lane], v1 = px[lane + 32], v2 = px[lane + 64];
            float s = v0 + v1 + v2, s2 = v0 * v0 + v1 * v1 + v2 * v2;
            #pragma unroll
            for (int o = 16; o; o >>= 1) {
                s  += __shfl_xor_sync(0xffffffffu, s, o);
                s2 += __shfl_xor_sync(0xffffffffu, s2, o);
            }
            float mu = s * (1.f / 96.f);
            float rs = rsqrtf(s2 * (1.f / 96.f) - mu * mu + 1e-5f);
            shH[n * HS2 + lane]      = (v0 - mu) * rs * w0 + c0;
            shH[n * HS2 + lane + 32] = (v1 - mu) * rs * wA + cA;
            shH[n * HS2 + lane + 64] = (v2 - mu) * rs * wB + cB;
        }
    }
    __syncthreads();

    const int rt = tid >> 4, ct = tid & 15;
    const int r0 = rt * 4, c0 = ct * 6;

    // fc1 + GELU, 4 column chunks of 96
    for (int cc = 0; cc < 4; ++cc) {
        for (int t = tid; t < 96 * 96; t += TPB) {
            int k = t / 96, c = t - k * 96;
            sW[t] = w1[k * 384 + cc * 96 + c];
        }
        __syncthreads();
        float acc[4][6] = {};
        #pragma unroll 4
        for (int k = 0; k < 96; ++k) {
            float a0 = shH[(r0 + 0) * HS2 + k];
            float a1 = shH[(r0 + 1) * HS2 + k];
            float a2 = shH[(r0 + 2) * HS2 + k];
            float a3 = shH[(r0 + 3) * HS2 + k];
            const float2* pb2 = (const float2*)(sW + k * 96 + c0);
            float2 q0 = pb2[0], q1 = pb2[1], q2 = pb2[2];
            float bv[6] = {q0.x, q0.y, q1.x, q1.y, q2.x, q2.y};
            #pragma unroll
            for (int j = 0; j < 6; ++j) {
                acc[0][j] += a0 * bv[j];
                acc[1][j] += a1 * bv[j];
                acc[2][j] += a2 * bv[j];
                acc[3][j] += a3 * bv[j];
            }
        }
        #pragma unroll
        for (int i = 0; i < 4; ++i) {
            #pragma unroll
            for (int j = 0; j < 6; ++j) {
                float v = acc[i][j] + b1[cc * 96 + c0 + j];
                float g = 0.5f * v * (1.f + erff(v * 0.70710678118654752f));
                sHid[(r0 + i) * HIDS + cc * 96 + c0 + j] = g;
            }
        }
        __syncthreads();
    }

    // fc2, 4 k-chunks of 96
    float acc2[4][6] = {};
    for (int kc = 0; kc < 4; ++kc) {
        for (int t = tid; t < 96 * 96; t += TPB) {
            int k = t / 96, c = t - k * 96;
            sW[t] = w2[(kc * 96 + k) * 96 + c];
        }
        __syncthreads();
        #pragma unroll 4
        for (int k = 0; k < 96; ++k) {
            float a0 = sHid[(r0 + 0) * HIDS + kc * 96 + k];
            float a1 = sHid[(r0 + 1) * HIDS + kc * 96 + k];
            float a2 = sHid[(r0 + 2) * HIDS + kc * 96 + k];
            float a3 = sHid[(r0 + 3) * HIDS + kc * 96 + k];
            const float2* pb2 = (const float2*)(sW + k * 96 + c0);
            float2 q0 = pb2[0], q1 = pb2[1], q2 = pb2[2];
            float bv[6] = {q0.x, q0.y, q1.x, q1.y, q2.x, q2.y};
            #pragma unroll
            for (int j = 0; j < 6; ++j) {
                acc2[0][j] += a0 * bv[j];
                acc2[1][j] += a1 * bv[j];
                acc2[2][j] += a2 * bv[j];
                acc2[3][j] += a3 * bv[j];
            }
        }
        __syncthreads();
    }

    #pragma unroll
    for (int i = 0; i < 4; ++i) {
        int gr = gr0 + r0 + i;
        const float* px = g_x1 + (size_t)gr * 96;
        float* pd = out + (size_t)gr * 96;
        #pragma unroll
        for (int j = 0; j < 6; ++j) {
            int c = c0 + j;
            pd[c] = acc2[i][j] + b2[c] + px[c];
        }
    }
}

extern "C" void kernel_launch(void* const* d_in, const int* in_sizes, int n_in,
                              void* d_out, int out_size)
{
    const float* x    = (const float*)d_in[0];
    const float* n1w  = (const float*)d_in[1];
    const float* n1b  = (const float*)d_in[2];
    const float* qkvw = (const float*)d_in[3];
    const float* qkvb = (const float*)d_in[4];
    const float* rpb  = (const float*)d_in[5];
    const float* pw   = (const float*)d_in[6];
    const float* pb   = (const float*)d_in[7];
    const float* n2w  = (const float*)d_in[8];
    const float* n2b  = (const float*)d_in[9];
    const float* w1   = (const float*)d_in[10];
    const float* b1   = (const float*)d_in[11];
    const float* w2   = (const float*)d_in[12];
    const float* b2   = (const float*)d_in[13];
    float* out = (float*)d_out;

    const int sm1 = SM1_FLOATS * 4;
    const int sm2 = SM2_FLOATS * 4;
    cudaFuncSetAttribute(attn_kernel, cudaFuncAttributeMaxDynamicSharedMemorySize, sm1);
    cudaFuncSetAttribute(mlp_kernel,  cudaFuncAttributeMaxDynamicSharedMemorySize, sm2);

    attn_kernel<<<4096, TPB, sm1>>>(x, n1w, n1b, qkvw, qkvb, rpb, pw, pb);
    mlp_kernel<<<4096, TPB, sm2>>>(n2w, n2b, w1, b1, w2, b2, out);
}

// round 6
// speedup vs baseline: 1.7454x; 1.7454x over previous
#include <cuda_runtime.h>
#include <cuda_bf16.h>
#include <math.h>
#include <stdint.h>

#define TPB 256

// scratch: x1 = shortcut + attn branch  (16*128*128*96 floats = ~100MB)
static __device__ float g_x1[16 * 128 * 128 * 96];

// ---------------- kernel 1: LN1 + shifted-window attention + proj + residual ----------------
constexpr int HS1    = 98;                 // padded row stride for 96-col tiles
constexpr int OFF_H  = 0;                  // LN'd window tokens      64 x HS1
constexpr int OFF_W  = OFF_H  + 64 * HS1;  // staged weights          96 x 96
constexpr int OFF_Q  = OFF_W  + 96 * 96;   // per-head Q              64 x 33
constexpr int OFF_K  = OFF_Q  + 64 * 33;   // per-head K              64 x 33
constexpr int OFF_V  = OFF_K  + 64 * 33;   // per-head V              64 x 33
constexpr int OFF_S  = OFF_V  + 64 * 33;   // scores / probs          64 x 65
constexpr int OFF_O  = OFF_S  + 64 * 65;   // concat head outputs     64 x HS1
constexpr int OFF_RPB= OFF_O  + 64 * HS1;  // rel-pos table           225 x 3
constexpr int OFF_REG= OFF_RPB + 675;      // region id per token     64 (int)
constexpr int OFF_SRC= OFF_REG + 64;       // gathered row index      64 (int)
constexpr int OFF_INV= OFF_SRC + 64;       // 1/rowsum                64
constexpr int SM1_FLOATS = OFF_INV + 64;

__global__ __launch_bounds__(TPB) void attn_kernel(
    const float* __restrict__ x,
    const float* __restrict__ n1w, const float* __restrict__ n1b,
    const float* __restrict__ qkvw, const float* __restrict__ qkvb,
    const float* __restrict__ rpb,
    const float* __restrict__ pw,  const float* __restrict__ pb)
{
    extern __shared__ float sm[];
    float* shH  = sm + OFF_H;
    float* sW   = sm + OFF_W;
    float* sQ   = sm + OFF_Q;
    float* sK   = sm + OFF_K;
    float* sV   = sm + OFF_V;
    float* sS   = sm + OFF_S;
    float* sO   = sm + OFF_O;
    float* sRPB = sm + OFF_RPB;
    int*   sReg = (int*)(sm + OFF_REG);
    int*   sSrc = (int*)(sm + OFF_SRC);
    float* sInv = sm + OFF_INV;

    const int tid = threadIdx.x;
    const int bw  = blockIdx.x;
    const int bb  = bw >> 8;          // batch
    const int wh  = (bw >> 4) & 15;   // window row
    const int ww  = bw & 15;          // window col
    const int baseRow = bb * (128 * 128);

    if (tid < 64) {
        int i = tid >> 3, j = tid & 7;
        int hr = wh * 8 + i, wr = ww * 8 + j;
        int hs = (hr + 4) & 127, ws = (wr + 4) & 127;
        sSrc[tid] = baseRow + hs * 128 + ws;
        int rh = hr < 120 ? 0 : (hr < 124 ? 1 : 2);
        int rw = wr < 120 ? 0 : (wr < 124 ? 1 : 2);
        sReg[tid] = rh * 3 + rw;
    }
    for (int t = tid; t < 675; t += TPB) sRPB[t] = rpb[t];

    {
        const int warp = tid >> 5, lane = tid & 31;
        float w0 = n1w[lane], w1 = n1w[lane + 32], w2 = n1w[lane + 64];
        float c0 = n1b[lane], c1 = n1b[lane + 32], c2 = n1b[lane + 64];
        for (int rr = 0; rr < 8; ++rr) {
            int n = warp * 8 + rr;
            int i = n >> 3, j = n & 7;
            int hs = (wh * 8 + i + 4) & 127, ws = (ww * 8 + j + 4) & 127;
            const float* px = x + (size_t)(baseRow + hs * 128 + ws) * 96;
            float v0 = px[lane], v1 = px[lane + 32], v2 = px[lane + 64];
            float s = v0 + v1 + v2, s2 = v0 * v0 + v1 * v1 + v2 * v2;
            #pragma unroll
            for (int o = 16; o; o >>= 1) {
                s  += __shfl_xor_sync(0xffffffffu, s, o);
                s2 += __shfl_xor_sync(0xffffffffu, s2, o);
            }
            float mu = s * (1.f / 96.f);
            float rs = rsqrtf(s2 * (1.f / 96.f) - mu * mu + 1e-5f);
            shH[n * HS1 + lane]      = (v0 - mu) * rs * w0 + c0;
            shH[n * HS1 + lane + 32] = (v1 - mu) * rs * w1 + c1;
            shH[n * HS1 + lane + 64] = (v2 - mu) * rs * w2 + c2;
        }
    }
    __syncthreads();

    const int rt = tid >> 4, ct = tid & 15;
    const int r0 = rt * 4, c0 = ct * 6;
    const float scale = 0.17677669529663687f;

    for (int h = 0; h < 3; ++h) {
        for (int t = tid; t < 96 * 96; t += TPB) {
            int k = t / 96, c = t - k * 96;
            int sec = c >> 5, d = c & 31;
            sW[t] = qkvw[k * 288 + sec * 96 + h * 32 + d];
        }
        __syncthreads();

        {
            float acc[4][6] = {};
            #pragma unroll 4
            for (int k = 0; k < 96; ++k) {
                float a0 = shH[(r0 + 0) * HS1 + k];
                float a1 = shH[(r0 + 1) * HS1 + k];
                float a2 = shH[(r0 + 2) * HS1 + k];
                float a3 = shH[(r0 + 3) * HS1 + k];
                const float2* pb2 = (const float2*)(sW + k * 96 + c0);
                float2 q0 = pb2[0], q1 = pb2[1], q2 = pb2[2];
                float bv[6] = {q0.x, q0.y, q1.x, q1.y, q2.x, q2.y};
                #pragma unroll
                for (int j = 0; j < 6; ++j) {
                    acc[0][j] += a0 * bv[j];
                    acc[1][j] += a1 * bv[j];
                    acc[2][j] += a2 * bv[j];
                    acc[3][j] += a3 * bv[j];
                }
            }
            #pragma unroll
            for (int j = 0; j < 6; ++j) {
                int c = c0 + j, sec = c >> 5, d = c & 31;
                float bias = qkvb[sec * 96 + h * 32 + d];
                float mul  = (sec == 0) ? scale : 1.f;
                float* dst = (sec == 0) ? sQ : (sec == 1) ? sK : sV;
                #pragma unroll
                for (int i = 0; i < 4; ++i)
                    dst[(r0 + i) * 33 + d] = (acc[i][j] + bias) * mul;
            }
        }
        __syncthreads();

        {
            int c0s = ct * 4;
            float acc[4][4] = {};
            #pragma unroll 4
            for (int d = 0; d < 32; ++d) {
                float a0 = sQ[(r0 + 0) * 33 + d];
                float a1 = sQ[(r0 + 1) * 33 + d];
                float a2 = sQ[(r0 + 2) * 33 + d];
                float a3 = sQ[(r0 + 3) * 33 + d];
                float b0 = sK[(c0s + 0) * 33 + d];
                float b1 = sK[(c0s + 1) * 33 + d];
                float b2 = sK[(c0s + 2) * 33 + d];
                float b3 = sK[(c0s + 3) * 33 + d];
                acc[0][0] += a0 * b0; acc[0][1] += a0 * b1; acc[0][2] += a0 * b2; acc[0][3] += a0 * b3;
                acc[1][0] += a1 * b0; acc[1][1] += a1 * b1; acc[1][2] += a1 * b2; acc[1][3] += a1 * b3;
                acc[2][0] += a2 * b0; acc[2][1] += a2 * b1; acc[2][2] += a2 * b2; acc[2][3] += a2 * b3;
                acc[3][0] += a3 * b0; acc[3][1] += a3 * b1; acc[3][2] += a3 * b2; acc[3][3] += a3 * b3;
            }
            #pragma unroll
            for (int i = 0; i < 4; ++i) {
                int n = r0 + i, iq = n >> 3, jq = n & 7, regn = sReg[n];
                #pragma unroll
                for (int j = 0; j < 4; ++j) {
                    int m = c0s + j, im = m >> 3, jm = m & 7;
                    float bias = sRPB[((iq - im + 7) * 15 + (jq - jm + 7)) * 3 + h];
                    float mv = (regn == sReg[m]) ? 0.f : -100.f;
                    sS[n * 65 + m] = acc[i][j] + bias + mv;
                }
            }
        }
        __syncthreads();

        {
            int row = tid >> 2, sub = tid & 3;
            float* prow = sS + row * 65 + sub * 16;
            float mx = prow[0];
            #pragma unroll
            for (int t = 1; t < 16; ++t) mx = fmaxf(mx, prow[t]);
            mx = fmaxf(mx, __shfl_xor_sync(0xffffffffu, mx, 1));
            mx = fmaxf(mx, __shfl_xor_sync(0xffffffffu, mx, 2));
            float sum = 0.f;
            #pragma unroll
            for (int t = 0; t < 16; ++t) {
                float e = __expf(prow[t] - mx);
                prow[t] = e;
                sum += e;
            }
            sum += __shfl_xor_sync(0xffffffffu, sum, 1);
            sum += __shfl_xor_sync(0xffffffffu, sum, 2);
            if (sub == 0) sInv[row] = 1.f / sum;
        }
        __syncthreads();

        {
            int rt2 = tid >> 3, ct2 = tid & 7;
            int ro = rt2 * 2, co = ct2 * 4;
            float acc[2][4] = {};
            #pragma unroll 4
            for (int m = 0; m < 64; ++m) {
                float a0 = sS[ro * 65 + m], a1 = sS[(ro + 1) * 65 + m];
                float b0 = sV[m * 33 + co + 0];
                float b1 = sV[m * 33 + co + 1];
                float b2 = sV[m * 33 + co + 2];
                float b3 = sV[m * 33 + co + 3];
                acc[0][0] += a0 * b0; acc[0][1] += a0 * b1; acc[0][2] += a0 * b2; acc[0][3] += a0 * b3;
                acc[1][0] += a1 * b0; acc[1][1] += a1 * b1; acc[1][2] += a1 * b2; acc[1][3] += a1 * b3;
            }
            float s0 = sInv[ro], s1 = sInv[ro + 1];
            #pragma unroll
            for (int j = 0; j < 4; ++j) {
                sO[ro * HS1 + h * 32 + co + j]       = acc[0][j] * s0;
                sO[(ro + 1) * HS1 + h * 32 + co + j] = acc[1][j] * s1;
            }
        }
        __syncthreads();
    }

    for (int t = tid; t < 96 * 96; t += TPB) sW[t] = pw[t];
    __syncthreads();
    {
        float acc[4][6] = {};
        #pragma unroll 4
        for (int k = 0; k < 96; ++k) {
            float a0 = sO[(r0 + 0) * HS1 + k];
            float a1 = sO[(r0 + 1) * HS1 + k];
            float a2 = sO[(r0 + 2) * HS1 + k];
            float a3 = sO[(r0 + 3) * HS1 + k];
            const float2* pb2 = (const float2*)(sW + k * 96 + c0);
            float2 q0 = pb2[0], q1 = pb2[1], q2 = pb2[2];
            float bv[6] = {q0.x, q0.y, q1.x, q1.y, q2.x, q2.y};
            #pragma unroll
            for (int j = 0; j < 6; ++j) {
                acc[0][j] += a0 * bv[j];
                acc[1][j] += a1 * bv[j];
                acc[2][j] += a2 * bv[j];
                acc[3][j] += a3 * bv[j];
            }
        }
        #pragma unroll
        for (int i = 0; i < 4; ++i) {
            int row = sSrc[r0 + i];
            const float* px = x + (size_t)row * 96;
            float* pd = g_x1 + (size_t)row * 96;
            #pragma unroll
            for (int j = 0; j < 6; ++j) {
                int c = c0 + j;
                pd[c] = acc[i][j] + pb[c] + px[c];
            }
        }
    }
}

// ---------------- kernel 2: LN2 + MLP via mma.sync bf16 (legacy tensor path) ----------------
// 256 thr = 8 warps; warp w owns rows w*16..w*16+15 of the CTA's 128-row tile.
// Hidden (384) chunked by 32: GEMM1 (m16 x n32, K=96) -> bias+GELU -> bf16 sH ->
// GEMM2 (m16 x n96, K=32) accumulated in d2[12][4] f32 registers across 12 chunks.
//
// smem halfs strides chosen so frag lds banks = (20g + t) % 32 (permutation, conflict-free):
//   sA  128 x 104 halfs, sW1 32 x 104, sH 128 x 40, sW2 96 x 40.
constexpr uint32_t MB_SA  = 0;                       // 26624 B
constexpr uint32_t MB_SW1 = 26624;                   // 6656 B
constexpr uint32_t MB_SH  = 33280;                   // 10240 B
constexpr uint32_t MB_SW2 = 43520;                   // 7680 B
constexpr uint32_t MB_B1  = 51200;                   // 32 f32
constexpr uint32_t MB_B2  = 51328;                   // 96 f32
constexpr uint32_t SM2_BYTES = 51712;

__device__ __forceinline__ void mma_bf16(float d[4],
    uint32_t a0, uint32_t a1, uint32_t a2, uint32_t a3, uint32_t b0, uint32_t b1)
{
    asm volatile(
        "mma.sync.aligned.m16n8k16.row.col.f32.bf16.bf16.f32 "
        "{%0,%1,%2,%3},{%4,%5,%6,%7},{%8,%9},{%0,%1,%2,%3};"
        : "+f"(d[0]), "+f"(d[1]), "+f"(d[2]), "+f"(d[3])
        : "r"(a0), "r"(a1), "r"(a2), "r"(a3), "r"(b0), "r"(b1));
}
__device__ __forceinline__ uint32_t pack_bf16(float lo, float hi) {
    uint32_t r;
    asm("cvt.rn.bf16x2.f32 %0, %1, %2;" : "=r"(r) : "f"(hi), "f"(lo)); // d.hi=%1, d.lo=%2
    return r;
}
__device__ __forceinline__ float gelu_exact(float v) {
    return 0.5f * v * (1.f + erff(v * 0.70710678118654752f));
}

__global__ __launch_bounds__(256, 2) void mlp_kernel(
    const float* __restrict__ n2w, const float* __restrict__ n2b,
    const float* __restrict__ w1,  const float* __restrict__ b1,
    const float* __restrict__ w2,  const float* __restrict__ b2,
    float* __restrict__ out)
{
    extern __shared__ char smc[];
    __nv_bfloat16* sA  = (__nv_bfloat16*)(smc + MB_SA);
    __nv_bfloat16* sW1 = (__nv_bfloat16*)(smc + MB_SW1);
    __nv_bfloat16* sH  = (__nv_bfloat16*)(smc + MB_SH);
    __nv_bfloat16* sW2 = (__nv_bfloat16*)(smc + MB_SW2);
    float* sB1 = (float*)(smc + MB_B1);
    float* sB2 = (float*)(smc + MB_B2);

    const int tid  = threadIdx.x;
    const int w    = tid >> 5;
    const int lane = tid & 31;
    const int g    = lane >> 2;      // group (row within tile)
    const int t    = lane & 3;       // thread-in-group (col pair)
    const int gr0  = blockIdx.x * 128;
    const int rowA = w * 16 + g;     // fragment base row within CTA tile

    if (tid < 96) sB2[tid] = b2[tid];

    // --- LN2 -> sA (bf16). warp handles rows w*16 .. w*16+15, lane covers 3 elems ---
    {
        float wv0 = n2w[lane], wv1 = n2w[lane + 32], wv2 = n2w[lane + 64];
        float bv0 = n2b[lane], bv1 = n2b[lane + 32], bv2 = n2b[lane + 64];
        for (int rr = 0; rr < 16; ++rr) {
            int n = w * 16 + rr;
            const float* px = g_x1 + (size_t)(gr0 + n) * 96;
            float v0 = px[lane], v1 = px[lane + 32], v2 = px[lane + 64];
            float s = v0 + v1 + v2, s2 = v0 * v0 + v1 * v1 + v2 * v2;
            #pragma unroll
            for (int o = 16; o; o >>= 1) {
                s  += __shfl_xor_sync(0xffffffffu, s, o);
                s2 += __shfl_xor_sync(0xffffffffu, s2, o);
            }
            float mu = s * (1.f / 96.f);
            float rs = rsqrtf(s2 * (1.f / 96.f) - mu * mu + 1e-5f);
            sA[n * 104 + lane]      = __float2bfloat16((v0 - mu) * rs * wv0 + bv0);
            sA[n * 104 + lane + 32] = __float2bfloat16((v1 - mu) * rs * wv1 + bv1);
            sA[n * 104 + lane + 64] = __float2bfloat16((v2 - mu) * rs * wv2 + bv2);
        }
    }
    __syncthreads();

    float d2[12][4];
    #pragma unroll
    for (int i = 0; i < 12; ++i)
        #pragma unroll
        for (int j = 0; j < 4; ++j) d2[i][j] = 0.f;

    for (int nc = 0; nc < 12; ++nc) {
        // ---- stage chunk weights (bf16, transposed to [n][k]) ----
        for (int idx = tid; idx < 3072; idx += 256) {
            int n = idx & 31, k = idx >> 5;
            sW1[n * 104 + k] = __float2bfloat16(w1[k * 384 + nc * 32 + n]);
        }
        for (int idx = tid; idx < 3072; idx += 256) {
            int n = idx % 96, k = idx / 96;
            sW2[n * 40 + k] = __float2bfloat16(w2[(nc * 32 + k) * 96 + n]);
        }
        if (tid < 32) sB1[tid] = b1[nc * 32 + tid];
        __syncthreads();

        // ---- GEMM1: d1(16 x 32) = A(16 x 96) @ W1c ----
        float d1[4][4];
        #pragma unroll
        for (int i = 0; i < 4; ++i)
            #pragma unroll
            for (int j = 0; j < 4; ++j) d1[i][j] = 0.f;

        #pragma unroll
        for (int kt = 0; kt < 6; ++kt) {
            uint32_t a0 = *(const uint32_t*)(sA + rowA * 104       + kt * 16 + 2 * t);
            uint32_t a1 = *(const uint32_t*)(sA + (rowA + 8) * 104 + kt * 16 + 2 * t);
            uint32_t a2 = *(const uint32_t*)(sA + rowA * 104       + kt * 16 + 2 * t + 8);
            uint32_t a3 = *(const uint32_t*)(sA + (rowA + 8) * 104 + kt * 16 + 2 * t + 8);
            #pragma unroll
            for (int nt = 0; nt < 4; ++nt) {
                uint32_t b0 = *(const uint32_t*)(sW1 + (nt * 8 + g) * 104 + kt * 16 + 2 * t);
                uint32_t b1r= *(const uint32_t*)(sW1 + (nt * 8 + g) * 104 + kt * 16 + 2 * t + 8);
                mma_bf16(d1[nt], a0, a1, a2, a3, b0, b1r);
            }
        }

        // ---- bias + exact GELU -> sH (bf16x2; C-frag layout == k16 A-frag layout) ----
        #pragma unroll
        for (int nt = 0; nt < 4; ++nt) {
            int c = nt * 8 + 2 * t;
            float bb0 = sB1[c], bb1 = sB1[c + 1];
            float v0 = gelu_exact(d1[nt][0] + bb0);
            float v1 = gelu_exact(d1[nt][1] + bb1);
            float v2 = gelu_exact(d1[nt][2] + bb0);
            float v3 = gelu_exact(d1[nt][3] + bb1);
            *(uint32_t*)(sH + rowA * 40       + c) = pack_bf16(v0, v1);
            *(uint32_t*)(sH + (rowA + 8) * 40 + c) = pack_bf16(v2, v3);
        }
        __syncwarp();

        // ---- GEMM2: d2(16 x 96) += H(16 x 32) @ W2c ----
        #pragma unroll
        for (int kt = 0; kt < 2; ++kt) {
            uint32_t a0 = *(const uint32_t*)(sH + rowA * 40       + kt * 16 + 2 * t);
            uint32_t a1 = *(const uint32_t*)(sH + (rowA + 8) * 40 + kt * 16 + 2 * t);
            uint32_t a2 = *(const uint32_t*)(sH + rowA * 40       + kt * 16 + 2 * t + 8);
            uint32_t a3 = *(const uint32_t*)(sH + (rowA + 8) * 40 + kt * 16 + 2 * t + 8);
            #pragma unroll
            for (int nt = 0; nt < 12; ++nt) {
                uint32_t b0 = *(const uint32_t*)(sW2 + (nt * 8 + g) * 40 + kt * 16 + 2 * t);
                uint32_t b1r= *(const uint32_t*)(sW2 + (nt * 8 + g) * 40 + kt * 16 + 2 * t + 8);
                mma_bf16(d2[nt], a0, a1, a2, a3, b0, b1r);
            }
        }
        __syncthreads();   // protect sW1/sW2/sB1 before next chunk's staging
    }

    // ---- epilogue: out = d2 + b2 + x1 ----
    #pragma unroll
    for (int nt = 0; nt < 12; ++nt) {
        int c = nt * 8 + 2 * t;
        float bb0 = sB2[c], bb1 = sB2[c + 1];
        size_t o1 = (size_t)(gr0 + rowA) * 96 + c;
        size_t o2 = (size_t)(gr0 + rowA + 8) * 96 + c;
        float2 xa = *(const float2*)(g_x1 + o1);
        float2 xb = *(const float2*)(g_x1 + o2);
        float2 r1, r2;
        r1.x = d2[nt][0] + bb0 + xa.x;  r1.y = d2[nt][1] + bb1 + xa.y;
        r2.x = d2[nt][2] + bb0 + xb.x;  r2.y = d2[nt][3] + bb1 + xb.y;
        *(float2*)(out + o1) = r1;
        *(float2*)(out + o2) = r2;
    }
}

extern "C" void kernel_launch(void* const* d_in, const int* in_sizes, int n_in,
                              void* d_out, int out_size)
{
    const float* x    = (const float*)d_in[0];
    const float* n1w  = (const float*)d_in[1];
    const float* n1b  = (const float*)d_in[2];
    const float* qkvw = (const float*)d_in[3];
    const float* qkvb = (const float*)d_in[4];
    const float* rpb  = (const float*)d_in[5];
    const float* pw   = (const float*)d_in[6];
    const float* pb   = (const float*)d_in[7];
    const float* n2w  = (const float*)d_in[8];
    const float* n2b  = (const float*)d_in[9];
    const float* w1   = (const float*)d_in[10];
    const float* b1   = (const float*)d_in[11];
    const float* w2   = (const float*)d_in[12];
    const float* b2   = (const float*)d_in[13];
    float* out = (float*)d_out;

    const int sm1 = SM1_FLOATS * 4;
    cudaFuncSetAttribute(attn_kernel, cudaFuncAttributeMaxDynamicSharedMemorySize, sm1);
    cudaFuncSetAttribute(mlp_kernel,  cudaFuncAttributeMaxDynamicSharedMemorySize, SM2_BYTES);

    attn_kernel<<<4096, TPB, sm1>>>(x, n1w, n1b, qkvw, qkvb, rpb, pw, pb);
    // 16*128*128 = 262144 token rows, 128 rows per CTA -> 2048 CTAs
    mlp_kernel<<<2048, 256, SM2_BYTES>>>(n2w, n2b, w1, b1, w2, b2, out);
}

// round 7
// speedup vs baseline: 3.9287x; 2.2509x over previous
#include <cuda_runtime.h>
#include <cuda_bf16.h>
#include <math.h>
#include <stdint.h>

// scratch: x1 = shortcut + attn branch  (16*128*128*96 floats = ~100MB)
static __device__ float g_x1[16 * 128 * 128 * 96];

// ===================== shared mma helpers =====================
__device__ __forceinline__ void mma_bf16(float d[4],
    uint32_t a0, uint32_t a1, uint32_t a2, uint32_t a3, uint32_t b0, uint32_t b1)
{
    asm volatile(
        "mma.sync.aligned.m16n8k16.row.col.f32.bf16.bf16.f32 "
        "{%0,%1,%2,%3},{%4,%5,%6,%7},{%8,%9},{%0,%1,%2,%3};"
        : "+f"(d[0]), "+f"(d[1]), "+f"(d[2]), "+f"(d[3])
        : "r"(a0), "r"(a1), "r"(a2), "r"(a3), "r"(b0), "r"(b1));
}
__device__ __forceinline__ uint32_t pack_bf16(float lo, float hi) {
    uint32_t r;
    asm("cvt.rn.bf16x2.f32 %0, %1, %2;" : "=r"(r) : "f"(hi), "f"(lo)); // d.hi=%1, d.lo=%2
    return r;
}
__device__ __forceinline__ float gelu_exact(float v) {
    return 0.5f * v * (1.f + erff(v * 0.70710678118654752f));
}

// ---------------- kernel 1: LN1 + shifted-window attention + proj + residual (bf16 mma) ----------------
// One CTA = 2 windows (128 token rows). 8 warps x 16-row tiles.
// Warps 0-3 = window A (ww = 2*wwp), warps 4-7 = window B (ww = 2*wwp+1).
// smem (bytes):
constexpr uint32_t AB_SA  = 0;        // sA   128 x 104 bf16 (LN'd tokens; reused for O before proj)
constexpr uint32_t AB_SW  = 26624;    // sW   96 x 104 bf16 (staged W^T chunk)
constexpr uint32_t AB_SQ  = 46592;    // sQ   128 x 40 bf16 (per-head Q, pre-scaled)
constexpr uint32_t AB_SK  = 56832;    // sK   128 x 40 bf16 (per-head K)
constexpr uint32_t AB_SVT = 67072;    // sVt  32 x 136 bf16 (per-head V transposed [dim][tok])
constexpr uint32_t AB_SP  = 75776;    // sP   128 x 72 bf16 (probs)
constexpr uint32_t AB_RPB = 94208;    // 675 f32 rel-pos table
constexpr uint32_t AB_REG = 96912;    // 128 int region ids
constexpr uint32_t AB_SRC = 97424;    // 128 int gathered row index
constexpr uint32_t AB_BIAS= 97936;    // 96 f32 staged bias
constexpr uint32_t SM1_BYTES = 98320;

__global__ __launch_bounds__(256, 2) void attn_kernel(
    const float* __restrict__ x,
    const float* __restrict__ n1w, const float* __restrict__ n1b,
    const float* __restrict__ qkvw, const float* __restrict__ qkvb,
    const float* __restrict__ rpb,
    const float* __restrict__ pw,  const float* __restrict__ pb)
{
    extern __shared__ char smc[];
    __nv_bfloat16* sA  = (__nv_bfloat16*)(smc + AB_SA);
    __nv_bfloat16* sW  = (__nv_bfloat16*)(smc + AB_SW);
    __nv_bfloat16* sQ  = (__nv_bfloat16*)(smc + AB_SQ);
    __nv_bfloat16* sK  = (__nv_bfloat16*)(smc + AB_SK);
    __nv_bfloat16* sVt = (__nv_bfloat16*)(smc + AB_SVT);
    __nv_bfloat16* sP  = (__nv_bfloat16*)(smc + AB_SP);
    float* sRPB = (float*)(smc + AB_RPB);
    int*   sReg = (int*)(smc + AB_REG);
    int*   sSrc = (int*)(smc + AB_SRC);
    float* sBias= (float*)(smc + AB_BIAS);

    const int tid  = threadIdx.x;
    const int w    = tid >> 5;
    const int lane = tid & 31;
    const int g    = lane >> 2;
    const int t    = lane & 3;
    const int rowA = w * 16 + g;

    const int bw  = blockIdx.x;
    const int bb  = bw >> 7;          // batch
    const int wh  = (bw >> 3) & 15;   // window row
    const int wwp = bw & 7;           // window-column pair
    const float scale = 0.17677669529663687f; // 1/sqrt(32)

    // per-token metadata
    if (tid < 128) {
        int win = tid >> 6, tok = tid & 63;
        int i = tok >> 3, j = tok & 7;
        int hr = wh * 8 + i, wr = (wwp * 2 + win) * 8 + j;
        int hs = (hr + 4) & 127, ws = (wr + 4) & 127;
        sSrc[tid] = bb * 16384 + hs * 128 + ws;
        int rh = hr < 120 ? 0 : (hr < 124 ? 1 : 2);
        int rw = wr < 120 ? 0 : (wr < 124 ? 1 : 2);
        sReg[tid] = rh * 3 + rw;
    }
    for (int q = tid; q < 675; q += 256) sRPB[q] = rpb[q];
    __syncthreads();

    // gather + LN1 -> sA bf16 (each warp its own 16 rows, lane covers 3 elems)
    {
        float wv0 = n1w[lane], wv1 = n1w[lane + 32], wv2 = n1w[lane + 64];
        float bv0 = n1b[lane], bv1 = n1b[lane + 32], bv2 = n1b[lane + 64];
        for (int rr = 0; rr < 16; ++rr) {
            int n = w * 16 + rr;
            const float* px = x + (size_t)sSrc[n] * 96;
            float v0 = px[lane], v1 = px[lane + 32], v2 = px[lane + 64];
            float s = v0 + v1 + v2, s2 = v0 * v0 + v1 * v1 + v2 * v2;
            #pragma unroll
            for (int o = 16; o; o >>= 1) {
                s  += __shfl_xor_sync(0xffffffffu, s, o);
                s2 += __shfl_xor_sync(0xffffffffu, s2, o);
            }
            float mu = s * (1.f / 96.f);
            float rs = rsqrtf(s2 * (1.f / 96.f) - mu * mu + 1e-5f);
            sA[n * 104 + lane]      = __float2bfloat16((v0 - mu) * rs * wv0 + bv0);
            sA[n * 104 + lane + 32] = __float2bfloat16((v1 - mu) * rs * wv1 + bv1);
            sA[n * 104 + lane + 64] = __float2bfloat16((v2 - mu) * rs * wv2 + bv2);
        }
    }
    __syncthreads();

    const int win = w >> 2;            // warp's window (0/1)
    const int wl  = w & 3;             // warp index within window
    float oacc[12][4];
    #pragma unroll
    for (int i = 0; i < 12; ++i)
        #pragma unroll
        for (int j = 0; j < 4; ++j) oacc[i][j] = 0.f;

    for (int h = 0; h < 3; ++h) {
        // ---- stage per-head W^T (cols: 0-31 Q, 32-63 K, 64-95 V) + bias ----
        for (int idx = tid; idx < 9216; idx += 256) {
            int n = idx % 96, k = idx / 96;
            int sec = n >> 5, d = n & 31;
            sW[n * 104 + k] = __float2bfloat16(qkvw[k * 288 + sec * 96 + h * 32 + d]);
        }
        if (tid < 96) {
            int sec = tid >> 5, d = tid & 31;
            sBias[tid] = qkvb[sec * 96 + h * 32 + d];
        }
        __syncthreads();

        // ---- QKV GEMM: d(16 x 96) = A(16 x 96) @ W ----
        {
            float d[12][4];
            #pragma unroll
            for (int i = 0; i < 12; ++i)
                #pragma unroll
                for (int j = 0; j < 4; ++j) d[i][j] = 0.f;
            #pragma unroll
            for (int kt = 0; kt < 6; ++kt) {
                uint32_t a0 = *(const uint32_t*)(sA + rowA * 104       + kt * 16 + 2 * t);
                uint32_t a1 = *(const uint32_t*)(sA + (rowA + 8) * 104 + kt * 16 + 2 * t);
                uint32_t a2 = *(const uint32_t*)(sA + rowA * 104       + kt * 16 + 2 * t + 8);
                uint32_t a3 = *(const uint32_t*)(sA + (rowA + 8) * 104 + kt * 16 + 2 * t + 8);
                #pragma unroll
                for (int nt = 0; nt < 12; ++nt) {
                    uint32_t b0 = *(const uint32_t*)(sW + (nt * 8 + g) * 104 + kt * 16 + 2 * t);
                    uint32_t b1r= *(const uint32_t*)(sW + (nt * 8 + g) * 104 + kt * 16 + 2 * t + 8);
                    mma_bf16(d[nt], a0, a1, a2, a3, b0, b1r);
                }
            }
            // epilogue: Q (scaled) / K row-major, V transposed
            #pragma unroll
            for (int nt = 0; nt < 12; ++nt) {
                int c = nt * 8 + 2 * t;
                float bb0 = sBias[c], bb1 = sBias[c + 1];
                float v0 = d[nt][0] + bb0, v1 = d[nt][1] + bb1;
                float v2 = d[nt][2] + bb0, v3 = d[nt][3] + bb1;
                if (nt < 4) {
                    *(uint32_t*)(sQ + rowA * 40       + c) = pack_bf16(v0 * scale, v1 * scale);
                    *(uint32_t*)(sQ + (rowA + 8) * 40 + c) = pack_bf16(v2 * scale, v3 * scale);
                } else if (nt < 8) {
                    int dim = c - 32;
                    *(uint32_t*)(sK + rowA * 40       + dim) = pack_bf16(v0, v1);
                    *(uint32_t*)(sK + (rowA + 8) * 40 + dim) = pack_bf16(v2, v3);
                } else {
                    int dim = c - 64;
                    sVt[dim * 136 + rowA]           = __float2bfloat16(v0);
                    sVt[(dim + 1) * 136 + rowA]     = __float2bfloat16(v1);
                    sVt[dim * 136 + rowA + 8]       = __float2bfloat16(v2);
                    sVt[(dim + 1) * 136 + rowA + 8] = __float2bfloat16(v3);
                }
            }
        }
        __syncthreads();

        // ---- scores: S(16 x 64) = Q(16 x 32) @ K^T (window-local) ----
        {
            float d1[8][4];
            #pragma unroll
            for (int i = 0; i < 8; ++i)
                #pragma unroll
                for (int j = 0; j < 4; ++j) d1[i][j] = 0.f;
            #pragma unroll
            for (int kt = 0; kt < 2; ++kt) {
                uint32_t a0 = *(const uint32_t*)(sQ + rowA * 40       + kt * 16 + 2 * t);
                uint32_t a1 = *(const uint32_t*)(sQ + (rowA + 8) * 40 + kt * 16 + 2 * t);
                uint32_t a2 = *(const uint32_t*)(sQ + rowA * 40       + kt * 16 + 2 * t + 8);
                uint32_t a3 = *(const uint32_t*)(sQ + (rowA + 8) * 40 + kt * 16 + 2 * t + 8);
                #pragma unroll
                for (int nt = 0; nt < 8; ++nt) {
                    int kr = win * 64 + nt * 8 + g;
                    uint32_t b0 = *(const uint32_t*)(sK + kr * 40 + kt * 16 + 2 * t);
                    uint32_t b1r= *(const uint32_t*)(sK + kr * 40 + kt * 16 + 2 * t + 8);
                    mma_bf16(d1[nt], a0, a1, a2, a3, b0, b1r);
                }
            }
            // rel-pos bias + shift mask (f32)
            int tokr0 = wl * 16 + g, tokr1 = tokr0 + 8;
            int iq0 = tokr0 >> 3, jq0 = tokr0 & 7;
            int iq1 = tokr1 >> 3, jq1 = tokr1 & 7;
            int reg0 = sReg[win * 64 + tokr0], reg1 = sReg[win * 64 + tokr1];
            #pragma unroll
            for (int nt = 0; nt < 8; ++nt) {
                #pragma unroll
                for (int jj = 0; jj < 2; ++jj) {
                    int m = nt * 8 + 2 * t + jj;
                    int im = m >> 3, jm = m & 7;
                    int regm = sReg[win * 64 + m];
                    d1[nt][jj]     += sRPB[((iq0 - im + 7) * 15 + (jq0 - jm + 7)) * 3 + h]
                                      + ((reg0 == regm) ? 0.f : -100.f);
                    d1[nt][2 + jj] += sRPB[((iq1 - im + 7) * 15 + (jq1 - jm + 7)) * 3 + h]
                                      + ((reg1 == regm) ? 0.f : -100.f);
                }
            }
            // softmax (rows g and g+8; quad shuffle over t)
            float mx0 = -1e30f, mx1 = -1e30f;
            #pragma unroll
            for (int nt = 0; nt < 8; ++nt) {
                mx0 = fmaxf(mx0, fmaxf(d1[nt][0], d1[nt][1]));
                mx1 = fmaxf(mx1, fmaxf(d1[nt][2], d1[nt][3]));
            }
            #pragma unroll
            for (int o = 1; o <= 2; o <<= 1) {
                mx0 = fmaxf(mx0, __shfl_xor_sync(0xffffffffu, mx0, o));
                mx1 = fmaxf(mx1, __shfl_xor_sync(0xffffffffu, mx1, o));
            }
            float sum0 = 0.f, sum1 = 0.f;
            #pragma unroll
            for (int nt = 0; nt < 8; ++nt) {
                d1[nt][0] = __expf(d1[nt][0] - mx0); sum0 += d1[nt][0];
                d1[nt][1] = __expf(d1[nt][1] - mx0); sum0 += d1[nt][1];
                d1[nt][2] = __expf(d1[nt][2] - mx1); sum1 += d1[nt][2];
                d1[nt][3] = __expf(d1[nt][3] - mx1); sum1 += d1[nt][3];
            }
            #pragma unroll
            for (int o = 1; o <= 2; o <<= 1) {
                sum0 += __shfl_xor_sync(0xffffffffu, sum0, o);
                sum1 += __shfl_xor_sync(0xffffffffu, sum1, o);
            }
            float inv0 = 1.f / sum0, inv1 = 1.f / sum1;
            #pragma unroll
            for (int nt = 0; nt < 8; ++nt) {
                int c = nt * 8 + 2 * t;
                *(uint32_t*)(sP + rowA * 72       + c) = pack_bf16(d1[nt][0] * inv0, d1[nt][1] * inv0);
                *(uint32_t*)(sP + (rowA + 8) * 72 + c) = pack_bf16(d1[nt][2] * inv1, d1[nt][3] * inv1);
            }
        }
        __syncwarp();

        // ---- PV: O_h(16 x 32) = P(16 x 64) @ V -> accumulate into oacc slots h*4.. ----
        #pragma unroll
        for (int kt = 0; kt < 4; ++kt) {
            uint32_t a0 = *(const uint32_t*)(sP + rowA * 72       + kt * 16 + 2 * t);
            uint32_t a1 = *(const uint32_t*)(sP + (rowA + 8) * 72 + kt * 16 + 2 * t);
            uint32_t a2 = *(const uint32_t*)(sP + rowA * 72       + kt * 16 + 2 * t + 8);
            uint32_t a3 = *(const uint32_t*)(sP + (rowA + 8) * 72 + kt * 16 + 2 * t + 8);
            #pragma unroll
            for (int nt = 0; nt < 4; ++nt) {
                int vb = (nt * 8 + g) * 136 + win * 64 + kt * 16 + 2 * t;
                uint32_t b0 = *(const uint32_t*)(sVt + vb);
                uint32_t b1r= *(const uint32_t*)(sVt + vb + 8);
                mma_bf16(oacc[h * 4 + nt], a0, a1, a2, a3, b0, b1r);
            }
        }
        __syncthreads();   // before restaging sW / overwriting sQ,sK,sVt,sP
    }

    // ---- O (concat heads) -> sA (reuse); stage proj weights ----
    #pragma unroll
    for (int nt = 0; nt < 12; ++nt) {
        int c = nt * 8 + 2 * t;
        *(uint32_t*)(sA + rowA * 104       + c) = pack_bf16(oacc[nt][0], oacc[nt][1]);
        *(uint32_t*)(sA + (rowA + 8) * 104 + c) = pack_bf16(oacc[nt][2], oacc[nt][3]);
    }
    for (int idx = tid; idx < 9216; idx += 256) {
        int n = idx % 96, k = idx / 96;
        sW[n * 104 + k] = __float2bfloat16(pw[k * 96 + n]);
    }
    if (tid < 96) sBias[tid] = pb[tid];
    __syncthreads();

    // ---- proj GEMM + residual + scatter ----
    {
        float d[12][4];
        #pragma unroll
        for (int i = 0; i < 12; ++i)
            #pragma unroll
            for (int j = 0; j < 4; ++j) d[i][j] = 0.f;
        #pragma unroll
        for (int kt = 0; kt < 6; ++kt) {
            uint32_t a0 = *(const uint32_t*)(sA + rowA * 104       + kt * 16 + 2 * t);
            uint32_t a1 = *(const uint32_t*)(sA + (rowA + 8) * 104 + kt * 16 + 2 * t);
            uint32_t a2 = *(const uint32_t*)(sA + rowA * 104       + kt * 16 + 2 * t + 8);
            uint32_t a3 = *(const uint32_t*)(sA + (rowA + 8) * 104 + kt * 16 + 2 * t + 8);
            #pragma unroll
            for (int nt = 0; nt < 12; ++nt) {
                uint32_t b0 = *(const uint32_t*)(sW + (nt * 8 + g) * 104 + kt * 16 + 2 * t);
                uint32_t b1r= *(const uint32_t*)(sW + (nt * 8 + g) * 104 + kt * 16 + 2 * t + 8);
                mma_bf16(d[nt], a0, a1, a2, a3, b0, b1r);
            }
        }
        int src0 = sSrc[rowA], src1 = sSrc[rowA + 8];
        const float* px0 = x + (size_t)src0 * 96;
        const float* px1 = x + (size_t)src1 * 96;
        float* pd0 = g_x1 + (size_t)src0 * 96;
        float* pd1 = g_x1 + (size_t)src1 * 96;
        #pragma unroll
        for (int nt = 0; nt < 12; ++nt) {
            int c = nt * 8 + 2 * t;
            float bb0 = sBias[c], bb1 = sBias[c + 1];
            float2 xa = *(const float2*)(px0 + c);
            float2 xb = *(const float2*)(px1 + c);
            float2 r1, r2;
            r1.x = d[nt][0] + bb0 + xa.x;  r1.y = d[nt][1] + bb1 + xa.y;
            r2.x = d[nt][2] + bb0 + xb.x;  r2.y = d[nt][3] + bb1 + xb.y;
            *(float2*)(pd0 + c) = r1;
            *(float2*)(pd1 + c) = r2;
        }
    }
}

// ---------------- kernel 2: LN2 + MLP via mma.sync bf16 (unchanged from R6 pass) ----------------
constexpr uint32_t MB_SA  = 0;                       // 26624 B
constexpr uint32_t MB_SW1 = 26624;                   // 6656 B
constexpr uint32_t MB_SH  = 33280;                   // 10240 B
constexpr uint32_t MB_SW2 = 43520;                   // 7680 B
constexpr uint32_t MB_B1  = 51200;                   // 32 f32
constexpr uint32_t MB_B2  = 51328;                   // 96 f32
constexpr uint32_t SM2_BYTES = 51712;

__global__ __launch_bounds__(256, 2) void mlp_kernel(
    const float* __restrict__ n2w, const float* __restrict__ n2b,
    const float* __restrict__ w1,  const float* __restrict__ b1,
    const float* __restrict__ w2,  const float* __restrict__ b2,
    float* __restrict__ out)
{
    extern __shared__ char smc[];
    __nv_bfloat16* sA  = (__nv_bfloat16*)(smc + MB_SA);
    __nv_bfloat16* sW1 = (__nv_bfloat16*)(smc + MB_SW1);
    __nv_bfloat16* sH  = (__nv_bfloat16*)(smc + MB_SH);
    __nv_bfloat16* sW2 = (__nv_bfloat16*)(smc + MB_SW2);
    float* sB1 = (float*)(smc + MB_B1);
    float* sB2 = (float*)(smc + MB_B2);

    const int tid  = threadIdx.x;
    const int w    = tid >> 5;
    const int lane = tid & 31;
    const int g    = lane >> 2;
    const int t    = lane & 3;
    const int gr0  = blockIdx.x * 128;
    const int rowA = w * 16 + g;

    if (tid < 96) sB2[tid] = b2[tid];

    {
        float wv0 = n2w[lane], wv1 = n2w[lane + 32], wv2 = n2w[lane + 64];
        float bv0 = n2b[lane], bv1 = n2b[lane + 32], bv2 = n2b[lane + 64];
        for (int rr = 0; rr < 16; ++rr) {
            int n = w * 16 + rr;
            const float* px = g_x1 + (size_t)(gr0 + n) * 96;
            float v0 = px[lane], v1 = px[lane + 32], v2 = px[lane + 64];
            float s = v0 + v1 + v2, s2 = v0 * v0 + v1 * v1 + v2 * v2;
            #pragma unroll
            for (int o = 16; o; o >>= 1) {
                s  += __shfl_xor_sync(0xffffffffu, s, o);
                s2 += __shfl_xor_sync(0xffffffffu, s2, o);
            }
            float mu = s * (1.f / 96.f);
            float rs = rsqrtf(s2 * (1.f / 96.f) - mu * mu + 1e-5f);
            sA[n * 104 + lane]      = __float2bfloat16((v0 - mu) * rs * wv0 + bv0);
            sA[n * 104 + lane + 32] = __float2bfloat16((v1 - mu) * rs * wv1 + bv1);
            sA[n * 104 + lane + 64] = __float2bfloat16((v2 - mu) * rs * wv2 + bv2);
        }
    }
    __syncthreads();

    float d2[12][4];
    #pragma unroll
    for (int i = 0; i < 12; ++i)
        #pragma unroll
        for (int j = 0; j < 4; ++j) d2[i][j] = 0.f;

    for (int nc = 0; nc < 12; ++nc) {
        for (int idx = tid; idx < 3072; idx += 256) {
            int n = idx & 31, k = idx >> 5;
            sW1[n * 104 + k] = __float2bfloat16(w1[k * 384 + nc * 32 + n]);
        }
        for (int idx = tid; idx < 3072; idx += 256) {
            int n = idx % 96, k = idx / 96;
            sW2[n * 40 + k] = __float2bfloat16(w2[(nc * 32 + k) * 96 + n]);
        }
        if (tid < 32) sB1[tid] = b1[nc * 32 + tid];
        __syncthreads();

        float d1[4][4];
        #pragma unroll
        for (int i = 0; i < 4; ++i)
            #pragma unroll
            for (int j = 0; j < 4; ++j) d1[i][j] = 0.f;

        #pragma unroll
        for (int kt = 0; kt < 6; ++kt) {
            uint32_t a0 = *(const uint32_t*)(sA + rowA * 104       + kt * 16 + 2 * t);
            uint32_t a1 = *(const uint32_t*)(sA + (rowA + 8) * 104 + kt * 16 + 2 * t);
            uint32_t a2 = *(const uint32_t*)(sA + rowA * 104       + kt * 16 + 2 * t + 8);
            uint32_t a3 = *(const uint32_t*)(sA + (rowA + 8) * 104 + kt * 16 + 2 * t + 8);
            #pragma unroll
            for (int nt = 0; nt < 4; ++nt) {
                uint32_t b0 = *(const uint32_t*)(sW1 + (nt * 8 + g) * 104 + kt * 16 + 2 * t);
                uint32_t b1r= *(const uint32_t*)(sW1 + (nt * 8 + g) * 104 + kt * 16 + 2 * t + 8);
                mma_bf16(d1[nt], a0, a1, a2, a3, b0, b1r);
            }
        }

        #pragma unroll
        for (int nt = 0; nt < 4; ++nt) {
            int c = nt * 8 + 2 * t;
            float bb0 = sB1[c], bb1 = sB1[c + 1];
            float v0 = gelu_exact(d1[nt][0] + bb0);
            float v1 = gelu_exact(d1[nt][1] + bb1);
            float v2 = gelu_exact(d1[nt][2] + bb0);
            float v3 = gelu_exact(d1[nt][3] + bb1);
            *(uint32_t*)(sH + rowA * 40       + c) = pack_bf16(v0, v1);
            *(uint32_t*)(sH + (rowA + 8) * 40 + c) = pack_bf16(v2, v3);
        }
        __syncwarp();

        #pragma unroll
        for (int kt = 0; kt < 2; ++kt) {
            uint32_t a0 = *(const uint32_t*)(sH + rowA * 40       + kt * 16 + 2 * t);
            uint32_t a1 = *(const uint32_t*)(sH + (rowA + 8) * 40 + kt * 16 + 2 * t);
            uint32_t a2 = *(const uint32_t*)(sH + rowA * 40       + kt * 16 + 2 * t + 8);
            uint32_t a3 = *(const uint32_t*)(sH + (rowA + 8) * 40 + kt * 16 + 2 * t + 8);
            #pragma unroll
            for (int nt = 0; nt < 12; ++nt) {
                uint32_t b0 = *(const uint32_t*)(sW2 + (nt * 8 + g) * 40 + kt * 16 + 2 * t);
                uint32_t b1r= *(const uint32_t*)(sW2 + (nt * 8 + g) * 40 + kt * 16 + 2 * t + 8);
                mma_bf16(d2[nt], a0, a1, a2, a3, b0, b1r);
            }
        }
        __syncthreads();
    }

    #pragma unroll
    for (int nt = 0; nt < 12; ++nt) {
        int c = nt * 8 + 2 * t;
        float bb0 = sB2[c], bb1 = sB2[c + 1];
        size_t o1 = (size_t)(gr0 + rowA) * 96 + c;
        size_t o2 = (size_t)(gr0 + rowA + 8) * 96 + c;
        float2 xa = *(const float2*)(g_x1 + o1);
        float2 xb = *(const float2*)(g_x1 + o2);
        float2 r1, r2;
        r1.x = d2[nt][0] + bb0 + xa.x;  r1.y = d2[nt][1] + bb1 + xa.y;
        r2.x = d2[nt][2] + bb0 + xb.x;  r2.y = d2[nt][3] + bb1 + xb.y;
        *(float2*)(out + o1) = r1;
        *(float2*)(out + o2) = r2;
    }
}

extern "C" void kernel_launch(void* const* d_in, const int* in_sizes, int n_in,
                              void* d_out, int out_size)
{
    const float* x    = (const float*)d_in[0];
    const float* n1w  = (const float*)d_in[1];
    const float* n1b  = (const float*)d_in[2];
    const float* qkvw = (const float*)d_in[3];
    const float* qkvb = (const float*)d_in[4];
    const float* rpb  = (const float*)d_in[5];
    const float* pw   = (const float*)d_in[6];
    const float* pb   = (const float*)d_in[7];
    const float* n2w  = (const float*)d_in[8];
    const float* n2b  = (const float*)d_in[9];
    const float* w1   = (const float*)d_in[10];
    const float* b1   = (const float*)d_in[11];
    const float* w2   = (const float*)d_in[12];
    const float* b2   = (const float*)d_in[13];
    float* out = (float*)d_out;

    cudaFuncSetAttribute(attn_kernel, cudaFuncAttributeMaxDynamicSharedMemorySize, SM1_BYTES);
    cudaFuncSetAttribute(mlp_kernel,  cudaFuncAttributeMaxDynamicSharedMemorySize, SM2_BYTES);

    // 16 batches x 16 window-rows x 8 window-column-pairs = 2048 CTAs, 2 windows each
    attn_kernel<<<2048, 256, SM1_BYTES>>>(x, n1w, n1b, qkvw, qkvb, rpb, pw, pb);
    // 262144 token rows / 128 rows per CTA = 2048 CTAs
    mlp_kernel<<<2048, 256, SM2_BYTES>>>(n2w, n2b, w1, b1, w2, b2, out);
}

// round 8
// speedup vs baseline: 5.1829x; 1.3193x over previous
#include <cuda_runtime.h>
#include <cuda_bf16.h>
#include <math.h>
#include <stdint.h>

// scratch: x1 = shortcut + attn branch  (16*128*128*96 floats = ~100MB)
static __device__ float g_x1[16 * 128 * 128 * 96];

// pre-converted bf16 weights in smem-ready layouts (written by prep_kernel each launch)
static __device__ __align__(16) __nv_bfloat16 g_wqkv[3 * 96 * 104];  // [h][n][k], stride 104
static __device__ __align__(16) __nv_bfloat16 g_wproj[96 * 104];     // [n][k]
static __device__ __align__(16) __nv_bfloat16 g_w1[12 * 32 * 104];   // [nc][n][k]
static __device__ __align__(16) __nv_bfloat16 g_w2[12 * 96 * 40];    // [nc][n][k]

__global__ void prep_kernel(
    const float* __restrict__ qkvw, const float* __restrict__ pw,
    const float* __restrict__ w1,   const float* __restrict__ w2)
{
    const int stride = gridDim.x * blockDim.x;
    const int tid0 = blockIdx.x * blockDim.x + threadIdx.x;
    // qkv: [h][n=sec*32+d][k] <- qkvw[k*288 + sec*96 + h*32 + d]
    for (int i = tid0; i < 3 * 96 * 96; i += stride) {
        int h = i / 9216, r = i - h * 9216, n = r / 96, k = r - n * 96;
        int sec = n >> 5, d = n & 31;
        g_wqkv[h * 9984 + n * 104 + k] = __float2bfloat16(qkvw[k * 288 + sec * 96 + h * 32 + d]);
    }
    // proj: [n][k] <- pw[k*96+n]
    for (int i = tid0; i < 96 * 96; i += stride) {
        int n = i / 96, k = i - n * 96;
        g_wproj[n * 104 + k] = __float2bfloat16(pw[k * 96 + n]);
    }
    // w1: [nc][n][k] <- w1[k*384 + nc*32 + n]
    for (int i = tid0; i < 96 * 384; i += stride) {
        int k = i / 384, c = i - k * 384;
        int nc = c >> 5, n = c & 31;
        g_w1[nc * 3328 + n * 104 + k] = __float2bfloat16(w1[i]);
    }
    // w2: [nc][n][kk] <- w2[(nc*32+kk)*96 + n]
    for (int i = tid0; i < 384 * 96; i += stride) {
        int kr = i / 96, n = i - kr * 96;
        int nc = kr >> 5, kk = kr & 31;
        g_w2[nc * 3840 + n * 40 + kk] = __float2bfloat16(w2[i]);
    }
}

// ===================== shared mma helpers =====================
__device__ __forceinline__ void mma_bf16(float d[4],
    uint32_t a0, uint32_t a1, uint32_t a2, uint32_t a3, uint32_t b0, uint32_t b1)
{
    asm volatile(
        "mma.sync.aligned.m16n8k16.row.col.f32.bf16.bf16.f32 "
        "{%0,%1,%2,%3},{%4,%5,%6,%7},{%8,%9},{%0,%1,%2,%3};"
        : "+f"(d[0]), "+f"(d[1]), "+f"(d[2]), "+f"(d[3])
        : "r"(a0), "r"(a1), "r"(a2), "r"(a3), "r"(b0), "r"(b1));
}
__device__ __forceinline__ uint32_t pack_bf16(float lo, float hi) {
    uint32_t r;
    asm("cvt.rn.bf16x2.f32 %0, %1, %2;" : "=r"(r) : "f"(hi), "f"(lo)); // d.hi=%1, d.lo=%2
    return r;
}
// tanh-based GELU: dev from exact erf-GELU < 1e-4 for |v|<2 (hidden sigma ~0.2),
// far below bf16 quantization of the stored activations.
__device__ __forceinline__ float gelu_fast(float v) {
    float u = v * (0.79788456f + 0.035677408f * v * v);
    float th; asm("tanh.approx.f32 %0, %1;" : "=f"(th) : "f"(u));
    return 0.5f * v * (1.f + th);
}

// ---------------- kernel 1: LN1 + shifted-window attention + proj + residual (bf16 mma) ----------------
constexpr uint32_t AB_SA  = 0;        // sA   128 x 104 bf16 (LN'd tokens; reused for O before proj)
constexpr uint32_t AB_SW  = 26624;    // sW   96 x 104 bf16 (staged W^T chunk)
constexpr uint32_t AB_SQ  = 46592;    // sQ   128 x 40 bf16 (per-head Q, pre-scaled)
constexpr uint32_t AB_SK  = 56832;    // sK   128 x 40 bf16 (per-head K)
constexpr uint32_t AB_SVT = 67072;    // sVt  32 x 136 bf16 (per-head V transposed [dim][tok])
constexpr uint32_t AB_SP  = 75776;    // sP   128 x 72 bf16 (probs)
constexpr uint32_t AB_RPB = 94208;    // 675 f32 rel-pos table
constexpr uint32_t AB_REG = 96912;    // 128 int region ids
constexpr uint32_t AB_SRC = 97424;    // 128 int gathered row index
constexpr uint32_t AB_BIAS= 97936;    // 96 f32 staged bias
constexpr uint32_t SM1_BYTES = 98320;

__global__ __launch_bounds__(256, 2) void attn_kernel(
    const float* __restrict__ x,
    const float* __restrict__ n1w, const float* __restrict__ n1b,
    const float* __restrict__ qkvb,
    const float* __restrict__ rpb,
    const float* __restrict__ pb)
{
    extern __shared__ char smc[];
    __nv_bfloat16* sA  = (__nv_bfloat16*)(smc + AB_SA);
    __nv_bfloat16* sW  = (__nv_bfloat16*)(smc + AB_SW);
    __nv_bfloat16* sQ  = (__nv_bfloat16*)(smc + AB_SQ);
    __nv_bfloat16* sK  = (__nv_bfloat16*)(smc + AB_SK);
    __nv_bfloat16* sVt = (__nv_bfloat16*)(smc + AB_SVT);
    __nv_bfloat16* sP  = (__nv_bfloat16*)(smc + AB_SP);
    float* sRPB = (float*)(smc + AB_RPB);
    int*   sReg = (int*)(smc + AB_REG);
    int*   sSrc = (int*)(smc + AB_SRC);
    float* sBias= (float*)(smc + AB_BIAS);

    const int tid  = threadIdx.x;
    const int w    = tid >> 5;
    const int lane = tid & 31;
    const int g    = lane >> 2;
    const int t    = lane & 3;
    const int rowA = w * 16 + g;

    const int bw  = blockIdx.x;
    const int bb  = bw >> 7;          // batch
    const int wh  = (bw >> 3) & 15;   // window row
    const int wwp = bw & 7;           // window-column pair
    const float scale = 0.17677669529663687f; // 1/sqrt(32)

    // per-token metadata
    if (tid < 128) {
        int win = tid >> 6, tok = tid & 63;
        int i = tok >> 3, j = tok & 7;
        int hr = wh * 8 + i, wr = (wwp * 2 + win) * 8 + j;
        int hs = (hr + 4) & 127, ws = (wr + 4) & 127;
        sSrc[tid] = bb * 16384 + hs * 128 + ws;
        int rh = hr < 120 ? 0 : (hr < 124 ? 1 : 2);
        int rw = wr < 120 ? 0 : (wr < 124 ? 1 : 2);
        sReg[tid] = rh * 3 + rw;
    }
    for (int q = tid; q < 675; q += 256) sRPB[q] = rpb[q];
    __syncthreads();

    // gather + LN1 -> sA bf16
    {
        float wv0 = n1w[lane], wv1 = n1w[lane + 32], wv2 = n1w[lane + 64];
        float bv0 = n1b[lane], bv1 = n1b[lane + 32], bv2 = n1b[lane + 64];
        for (int rr = 0; rr < 16; ++rr) {
            int n = w * 16 + rr;
            const float* px = x + (size_t)sSrc[n] * 96;
            float v0 = px[lane], v1 = px[lane + 32], v2 = px[lane + 64];
            float s = v0 + v1 + v2, s2 = v0 * v0 + v1 * v1 + v2 * v2;
            #pragma unroll
            for (int o = 16; o; o >>= 1) {
                s  += __shfl_xor_sync(0xffffffffu, s, o);
                s2 += __shfl_xor_sync(0xffffffffu, s2, o);
            }
            float mu = s * (1.f / 96.f);
            float rs = rsqrtf(s2 * (1.f / 96.f) - mu * mu + 1e-5f);
            sA[n * 104 + lane]      = __float2bfloat16((v0 - mu) * rs * wv0 + bv0);
            sA[n * 104 + lane + 32] = __float2bfloat16((v1 - mu) * rs * wv1 + bv1);
            sA[n * 104 + lane + 64] = __float2bfloat16((v2 - mu) * rs * wv2 + bv2);
        }
    }
    __syncthreads();

    const int win = w >> 2;            // warp's window (0/1)
    const int wl  = w & 3;             // warp index within window
    float oacc[12][4];
    #pragma unroll
    for (int i = 0; i < 12; ++i)
        #pragma unroll
        for (int j = 0; j < 4; ++j) oacc[i][j] = 0.f;

    for (int h = 0; h < 3; ++h) {
        // ---- stage per-head W (pre-transposed bf16): 1248 uint4 ----
        {
            const uint4* src = (const uint4*)(g_wqkv + h * 9984);
            uint4* dst = (uint4*)sW;
            for (int i = tid; i < 1248; i += 256) dst[i] = src[i];
        }
        if (tid < 96) {
            int sec = tid >> 5, d = tid & 31;
            sBias[tid] = qkvb[sec * 96 + h * 32 + d];
        }
        __syncthreads();

        // ---- QKV GEMM: d(16 x 96) = A(16 x 96) @ W ----
        {
            float d[12][4];
            #pragma unroll
            for (int i = 0; i < 12; ++i)
                #pragma unroll
                for (int j = 0; j < 4; ++j) d[i][j] = 0.f;
            #pragma unroll
            for (int kt = 0; kt < 6; ++kt) {
                uint32_t a0 = *(const uint32_t*)(sA + rowA * 104       + kt * 16 + 2 * t);
                uint32_t a1 = *(const uint32_t*)(sA + (rowA + 8) * 104 + kt * 16 + 2 * t);
                uint32_t a2 = *(const uint32_t*)(sA + rowA * 104       + kt * 16 + 2 * t + 8);
                uint32_t a3 = *(const uint32_t*)(sA + (rowA + 8) * 104 + kt * 16 + 2 * t + 8);
                #pragma unroll
                for (int nt = 0; nt < 12; ++nt) {
                    uint32_t b0 = *(const uint32_t*)(sW + (nt * 8 + g) * 104 + kt * 16 + 2 * t);
                    uint32_t b1r= *(const uint32_t*)(sW + (nt * 8 + g) * 104 + kt * 16 + 2 * t + 8);
                    mma_bf16(d[nt], a0, a1, a2, a3, b0, b1r);
                }
            }
            #pragma unroll
            for (int nt = 0; nt < 12; ++nt) {
                int c = nt * 8 + 2 * t;
                float bb0 = sBias[c], bb1 = sBias[c + 1];
                float v0 = d[nt][0] + bb0, v1 = d[nt][1] + bb1;
                float v2 = d[nt][2] + bb0, v3 = d[nt][3] + bb1;
                if (nt < 4) {
                    *(uint32_t*)(sQ + rowA * 40       + c) = pack_bf16(v0 * scale, v1 * scale);
                    *(uint32_t*)(sQ + (rowA + 8) * 40 + c) = pack_bf16(v2 * scale, v3 * scale);
                } else if (nt < 8) {
                    int dim = c - 32;
                    *(uint32_t*)(sK + rowA * 40       + dim) = pack_bf16(v0, v1);
                    *(uint32_t*)(sK + (rowA + 8) * 40 + dim) = pack_bf16(v2, v3);
                } else {
                    int dim = c - 64;
                    sVt[dim * 136 + rowA]           = __float2bfloat16(v0);
                    sVt[(dim + 1) * 136 + rowA]     = __float2bfloat16(v1);
                    sVt[dim * 136 + rowA + 8]       = __float2bfloat16(v2);
                    sVt[(dim + 1) * 136 + rowA + 8] = __float2bfloat16(v3);
                }
            }
        }
        __syncthreads();

        // ---- scores: S(16 x 64) = Q(16 x 32) @ K^T (window-local) ----
        {
            float d1[8][4];
            #pragma unroll
            for (int i = 0; i < 8; ++i)
                #pragma unroll
                for (int j = 0; j < 4; ++j) d1[i][j] = 0.f;
            #pragma unroll
            for (int kt = 0; kt < 2; ++kt) {
                uint32_t a0 = *(const uint32_t*)(sQ + rowA * 40       + kt * 16 + 2 * t);
                uint32_t a1 = *(const uint32_t*)(sQ + (rowA + 8) * 40 + kt * 16 + 2 * t);
                uint32_t a2 = *(const uint32_t*)(sQ + rowA * 40       + kt * 16 + 2 * t + 8);
                uint32_t a3 = *(const uint32_t*)(sQ + (rowA + 8) * 40 + kt * 16 + 2 * t + 8);
                #pragma unroll
                for (int nt = 0; nt < 8; ++nt) {
                    int kr = win * 64 + nt * 8 + g;
                    uint32_t b0 = *(const uint32_t*)(sK + kr * 40 + kt * 16 + 2 * t);
                    uint32_t b1r= *(const uint32_t*)(sK + kr * 40 + kt * 16 + 2 * t + 8);
                    mma_bf16(d1[nt], a0, a1, a2, a3, b0, b1r);
                }
            }
            int tokr0 = wl * 16 + g, tokr1 = tokr0 + 8;
            int iq0 = tokr0 >> 3, jq0 = tokr0 & 7;
            int iq1 = tokr1 >> 3, jq1 = tokr1 & 7;
            int reg0 = sReg[win * 64 + tokr0], reg1 = sReg[win * 64 + tokr1];
            #pragma unroll
            for (int nt = 0; nt < 8; ++nt) {
                #pragma unroll
                for (int jj = 0; jj < 2; ++jj) {
                    int m = nt * 8 + 2 * t + jj;
                    int im = m >> 3, jm = m & 7;
                    int regm = sReg[win * 64 + m];
                    d1[nt][jj]     += sRPB[((iq0 - im + 7) * 15 + (jq0 - jm + 7)) * 3 + h]
                                      + ((reg0 == regm) ? 0.f : -100.f);
                    d1[nt][2 + jj] += sRPB[((iq1 - im + 7) * 15 + (jq1 - jm + 7)) * 3 + h]
                                      + ((reg1 == regm) ? 0.f : -100.f);
                }
            }
            float mx0 = -1e30f, mx1 = -1e30f;
            #pragma unroll
            for (int nt = 0; nt < 8; ++nt) {
                mx0 = fmaxf(mx0, fmaxf(d1[nt][0], d1[nt][1]));
                mx1 = fmaxf(mx1, fmaxf(d1[nt][2], d1[nt][3]));
            }
            #pragma unroll
            for (int o = 1; o <= 2; o <<= 1) {
                mx0 = fmaxf(mx0, __shfl_xor_sync(0xffffffffu, mx0, o));
                mx1 = fmaxf(mx1, __shfl_xor_sync(0xffffffffu, mx1, o));
            }
            float sum0 = 0.f, sum1 = 0.f;
            #pragma unroll
            for (int nt = 0; nt < 8; ++nt) {
                d1[nt][0] = __expf(d1[nt][0] - mx0); sum0 += d1[nt][0];
                d1[nt][1] = __expf(d1[nt][1] - mx0); sum0 += d1[nt][1];
                d1[nt][2] = __expf(d1[nt][2] - mx1); sum1 += d1[nt][2];
                d1[nt][3] = __expf(d1[nt][3] - mx1); sum1 += d1[nt][3];
            }
            #pragma unroll
            for (int o = 1; o <= 2; o <<= 1) {
                sum0 += __shfl_xor_sync(0xffffffffu, sum0, o);
                sum1 += __shfl_xor_sync(0xffffffffu, sum1, o);
            }
            float inv0 = 1.f / sum0, inv1 = 1.f / sum1;
            #pragma unroll
            for (int nt = 0; nt < 8; ++nt) {
                int c = nt * 8 + 2 * t;
                *(uint32_t*)(sP + rowA * 72       + c) = pack_bf16(d1[nt][0] * inv0, d1[nt][1] * inv0);
                *(uint32_t*)(sP + (rowA + 8) * 72 + c) = pack_bf16(d1[nt][2] * inv1, d1[nt][3] * inv1);
            }
        }
        __syncwarp();

        // ---- PV: O_h(16 x 32) = P(16 x 64) @ V ----
        #pragma unroll
        for (int kt = 0; kt < 4; ++kt) {
            uint32_t a0 = *(const uint32_t*)(sP + rowA * 72       + kt * 16 + 2 * t);
            uint32_t a1 = *(const uint32_t*)(sP + (rowA + 8) * 72 + kt * 16 + 2 * t);
            uint32_t a2 = *(const uint32_t*)(sP + rowA * 72       + kt * 16 + 2 * t + 8);
            uint32_t a3 = *(const uint32_t*)(sP + (rowA + 8) * 72 + kt * 16 + 2 * t + 8);
            #pragma unroll
            for (int nt = 0; nt < 4; ++nt) {
                int vb = (nt * 8 + g) * 136 + win * 64 + kt * 16 + 2 * t;
                uint32_t b0 = *(const uint32_t*)(sVt + vb);
                uint32_t b1r= *(const uint32_t*)(sVt + vb + 8);
                mma_bf16(oacc[h * 4 + nt], a0, a1, a2, a3, b0, b1r);
            }
        }
        __syncthreads();
    }

    // ---- O (concat heads) -> sA (reuse); stage proj weights ----
    #pragma unroll
    for (int nt = 0; nt < 12; ++nt) {
        int c = nt * 8 + 2 * t;
        *(uint32_t*)(sA + rowA * 104       + c) = pack_bf16(oacc[nt][0], oacc[nt][1]);
        *(uint32_t*)(sA + (rowA + 8) * 104 + c) = pack_bf16(oacc[nt][2], oacc[nt][3]);
    }
    {
        const uint4* src = (const uint4*)g_wproj;
        uint4* dst = (uint4*)sW;
        for (int i = tid; i < 1248; i += 256) dst[i] = src[i];
    }
    if (tid < 96) sBias[tid] = pb[tid];
    __syncthreads();

    // ---- proj GEMM + residual + scatter ----
    {
        float d[12][4];
        #pragma unroll
        for (int i = 0; i < 12; ++i)
            #pragma unroll
            for (int j = 0; j < 4; ++j) d[i][j] = 0.f;
        #pragma unroll
        for (int kt = 0; kt < 6; ++kt) {
            uint32_t a0 = *(const uint32_t*)(sA + rowA * 104       + kt * 16 + 2 * t);
            uint32_t a1 = *(const uint32_t*)(sA + (rowA + 8) * 104 + kt * 16 + 2 * t);
            uint32_t a2 = *(const uint32_t*)(sA + rowA * 104       + kt * 16 + 2 * t + 8);
            uint32_t a3 = *(const uint32_t*)(sA + (rowA + 8) * 104 + kt * 16 + 2 * t + 8);
            #pragma unroll
            for (int nt = 0; nt < 12; ++nt) {
                uint32_t b0 = *(const uint32_t*)(sW + (nt * 8 + g) * 104 + kt * 16 + 2 * t);
                uint32_t b1r= *(const uint32_t*)(sW + (nt * 8 + g) * 104 + kt * 16 + 2 * t + 8);
                mma_bf16(d[nt], a0, a1, a2, a3, b0, b1r);
            }
        }
        int src0 = sSrc[rowA], src1 = sSrc[rowA + 8];
        const float* px0 = x + (size_t)src0 * 96;
        const float* px1 = x + (size_t)src1 * 96;
        float* pd0 = g_x1 + (size_t)src0 * 96;
        float* pd1 = g_x1 + (size_t)src1 * 96;
        #pragma unroll
        for (int nt = 0; nt < 12; ++nt) {
            int c = nt * 8 + 2 * t;
            float bb0 = sBias[c], bb1 = sBias[c + 1];
            float2 xa = *(const float2*)(px0 + c);
            float2 xb = *(const float2*)(px1 + c);
            float2 r1, r2;
            r1.x = d[nt][0] + bb0 + xa.x;  r1.y = d[nt][1] + bb1 + xa.y;
            r2.x = d[nt][2] + bb0 + xb.x;  r2.y = d[nt][3] + bb1 + xb.y;
            *(float2*)(pd0 + c) = r1;
            *(float2*)(pd1 + c) = r2;
        }
    }
}

// ---------------- kernel 2: LN2 + MLP via mma.sync bf16 ----------------
constexpr uint32_t MB_SA  = 0;                       // 26624 B
constexpr uint32_t MB_SW1 = 26624;                   // 6656 B
constexpr uint32_t MB_SH  = 33280;                   // 10240 B
constexpr uint32_t MB_SW2 = 43520;                   // 7680 B
constexpr uint32_t MB_B1  = 51200;                   // 32 f32
constexpr uint32_t MB_B2  = 51328;                   // 96 f32
constexpr uint32_t SM2_BYTES = 51712;

__global__ __launch_bounds__(256, 2) void mlp_kernel(
    const float* __restrict__ n2w, const float* __restrict__ n2b,
    const float* __restrict__ b1,  const float* __restrict__ b2,
    float* __restrict__ out)
{
    extern __shared__ char smc[];
    __nv_bfloat16* sA  = (__nv_bfloat16*)(smc + MB_SA);
    __nv_bfloat16* sW1 = (__nv_bfloat16*)(smc + MB_SW1);
    __nv_bfloat16* sH  = (__nv_bfloat16*)(smc + MB_SH);
    __nv_bfloat16* sW2 = (__nv_bfloat16*)(smc + MB_SW2);
    float* sB1 = (float*)(smc + MB_B1);
    float* sB2 = (float*)(smc + MB_B2);

    const int tid  = threadIdx.x;
    const int w    = tid >> 5;
    const int lane = tid & 31;
    const int g    = lane >> 2;
    const int t    = lane & 3;
    const int gr0  = blockIdx.x * 128;
    const int rowA = w * 16 + g;

    if (tid < 96) sB2[tid] = b2[tid];

    {
        float wv0 = n2w[lane], wv1 = n2w[lane + 32], wv2 = n2w[lane + 64];
        float bv0 = n2b[lane], bv1 = n2b[lane + 32], bv2 = n2b[lane + 64];
        for (int rr = 0; rr < 16; ++rr) {
            int n = w * 16 + rr;
            const float* px = g_x1 + (size_t)(gr0 + n) * 96;
            float v0 = px[lane], v1 = px[lane + 32], v2 = px[lane + 64];
            float s = v0 + v1 + v2, s2 = v0 * v0 + v1 * v1 + v2 * v2;
            #pragma unroll
            for (int o = 16; o; o >>= 1) {
                s  += __shfl_xor_sync(0xffffffffu, s, o);
                s2 += __shfl_xor_sync(0xffffffffu, s2, o);
            }
            float mu = s * (1.f / 96.f);
            float rs = rsqrtf(s2 * (1.f / 96.f) - mu * mu + 1e-5f);
            sA[n * 104 + lane]      = __float2bfloat16((v0 - mu) * rs * wv0 + bv0);
            sA[n * 104 + lane + 32] = __float2bfloat16((v1 - mu) * rs * wv1 + bv1);
            sA[n * 104 + lane + 64] = __float2bfloat16((v2 - mu) * rs * wv2 + bv2);
        }
    }
    __syncthreads();

    float d2[12][4];
    #pragma unroll
    for (int i = 0; i < 12; ++i)
        #pragma unroll
        for (int j = 0; j < 4; ++j) d2[i][j] = 0.f;

    for (int nc = 0; nc < 12; ++nc) {
        // ---- stage chunk weights (pre-converted bf16): 416 + 480 uint4 ----
        {
            const uint4* src1 = (const uint4*)(g_w1 + nc * 3328);
            uint4* dst1 = (uint4*)sW1;
            for (int i = tid; i < 416; i += 256) dst1[i] = src1[i];
            const uint4* src2 = (const uint4*)(g_w2 + nc * 3840);
            uint4* dst2 = (uint4*)sW2;
            for (int i = tid; i < 480; i += 256) dst2[i] = src2[i];
        }
        if (tid < 32) sB1[tid] = b1[nc * 32 + tid];
        __syncthreads();

        float d1[4][4];
        #pragma unroll
        for (int i = 0; i < 4; ++i)
            #pragma unroll
            for (int j = 0; j < 4; ++j) d1[i][j] = 0.f;

        #pragma unroll
        for (int kt = 0; kt < 6; ++kt) {
            uint32_t a0 = *(const uint32_t*)(sA + rowA * 104       + kt * 16 + 2 * t);
            uint32_t a1 = *(const uint32_t*)(sA + (rowA + 8) * 104 + kt * 16 + 2 * t);
            uint32_t a2 = *(const uint32_t*)(sA + rowA * 104       + kt * 16 + 2 * t + 8);
            uint32_t a3 = *(const uint32_t*)(sA + (rowA + 8) * 104 + kt * 16 + 2 * t + 8);
            #pragma unroll
            for (int nt = 0; nt < 4; ++nt) {
                uint32_t b0 = *(const uint32_t*)(sW1 + (nt * 8 + g) * 104 + kt * 16 + 2 * t);
                uint32_t b1r= *(const uint32_t*)(sW1 + (nt * 8 + g) * 104 + kt * 16 + 2 * t + 8);
                mma_bf16(d1[nt], a0, a1, a2, a3, b0, b1r);
            }
        }

        #pragma unroll
        for (int nt = 0; nt < 4; ++nt) {
            int c = nt * 8 + 2 * t;
            float bb0 = sB1[c], bb1 = sB1[c + 1];
            float v0 = gelu_fast(d1[nt][0] + bb0);
            float v1 = gelu_fast(d1[nt][1] + bb1);
            float v2 = gelu_fast(d1[nt][2] + bb0);
            float v3 = gelu_fast(d1[nt][3] + bb1);
            *(uint32_t*)(sH + rowA * 40       + c) = pack_bf16(v0, v1);
            *(uint32_t*)(sH + (rowA + 8) * 40 + c) = pack_bf16(v2, v3);
        }
        __syncwarp();

        #pragma unroll
        for (int kt = 0; kt < 2; ++kt) {
            uint32_t a0 = *(const uint32_t*)(sH + rowA * 40       + kt * 16 + 2 * t);
            uint32_t a1 = *(const uint32_t*)(sH + (rowA + 8) * 40 + kt * 16 + 2 * t);
            uint32_t a2 = *(const uint32_t*)(sH + rowA * 40       + kt * 16 + 2 * t + 8);
            uint32_t a3 = *(const uint32_t*)(sH + (rowA + 8) * 40 + kt * 16 + 2 * t + 8);
            #pragma unroll
            for (int nt = 0; nt < 12; ++nt) {
                uint32_t b0 = *(const uint32_t*)(sW2 + (nt * 8 + g) * 40 + kt * 16 + 2 * t);
                uint32_t b1r= *(const uint32_t*)(sW2 + (nt * 8 + g) * 40 + kt * 16 + 2 * t + 8);
                mma_bf16(d2[nt], a0, a1, a2, a3, b0, b1r);
            }
        }
        __syncthreads();
    }

    #pragma unroll
    for (int nt = 0; nt < 12; ++nt) {
        int c = nt * 8 + 2 * t;
        float bb0 = sB2[c], bb1 = sB2[c + 1];
        size_t o1 = (size_t)(gr0 + rowA) * 96 + c;
        size_t o2 = (size_t)(gr0 + rowA + 8) * 96 + c;
        float2 xa = *(const float2*)(g_x1 + o1);
        float2 xb = *(const float2*)(g_x1 + o2);
        float2 r1, r2;
        r1.x = d2[nt][0] + bb0 + xa.x;  r1.y = d2[nt][1] + bb1 + xa.y;
        r2.x = d2[nt][2] + bb0 + xb.x;  r2.y = d2[nt][3] + bb1 + xb.y;
        *(float2*)(out + o1) = r1;
        *(float2*)(out + o2) = r2;
    }
}

extern "C" void kernel_launch(void* const* d_in, const int* in_sizes, int n_in,
                              void* d_out, int out_size)
{
    const float* x    = (const float*)d_in[0];
    const float* n1w  = (const float*)d_in[1];
    const float* n1b  = (const float*)d_in[2];
    const float* qkvw = (const float*)d_in[3];
    const float* qkvb = (const float*)d_in[4];
    const float* rpb  = (const float*)d_in[5];
    const float* pw   = (const float*)d_in[6];
    const float* pb   = (const float*)d_in[7];
    const float* n2w  = (const float*)d_in[8];
    const float* n2b  = (const float*)d_in[9];
    const float* w1   = (const float*)d_in[10];
    const float* b1   = (const float*)d_in[11];
    const float* w2   = (const float*)d_in[12];
    const float* b2   = (const float*)d_in[13];
    float* out = (float*)d_out;

    cudaFuncSetAttribute(attn_kernel, cudaFuncAttributeMaxDynamicSharedMemorySize, SM1_BYTES);
    cudaFuncSetAttribute(mlp_kernel,  cudaFuncAttributeMaxDynamicSharedMemorySize, SM2_BYTES);

    prep_kernel<<<64, 256>>>(qkvw, pw, w1, w2);
    attn_kernel<<<2048, 256, SM1_BYTES>>>(x, n1w, n1b, qkvb, rpb, pb);
    mlp_kernel<<<2048, 256, SM2_BYTES>>>(n2w, n2b, b1, b2, out);
}